// round 16
// baseline (speedup 1.0000x reference)
#include <cuda_runtime.h>
#include <cuda_bf16.h>
#include <cstdint>
#include <math.h>

// Problem constants
#define BB   2
#define SS   2048
#define DM   1024
#define NH   16
#define DH   64
#define MM   (BB*SS)

// -------- scratch (device globals; allocation-free) --------
__device__ float g_q[BB*NH*SS*DH];                   // [b][h][s][d] tf32 bits
__device__ float g_k[BB*NH*SS*DH];
__device__ float g_v[BB*NH*SS*DH];
__device__ __align__(16) float g_xt[MM*DM];          // X  (tf32-rounded fp32)
__device__ __align__(16) float g_wt[3*DM*DM];        // Wq,Wk,Wv (tf32)
__device__ __align__(16) float g_wot[DM*DM];         // Wo (tf32)
__device__ __align__(16) float g_ct[MM*DM];          // ctx (tf32, from attention)

// ============================================================
// helpers
// ============================================================
__device__ __forceinline__ uint32_t smem_u32(const void* p) {
    uint32_t a;
    asm("{ .reg .u64 t; cvta.to.shared.u64 t, %1; cvt.u32.u64 %0, t; }" : "=r"(a) : "l"(p));
    return a;
}
__device__ __forceinline__ uint32_t cvt_tf32(float a) {
    uint32_t r;
    asm("cvt.rna.tf32.f32 %0, %1;" : "=r"(r) : "f"(a));
    return r;
}
__device__ __forceinline__ float ex2_fast(float x) {
    float r;
    asm("ex2.approx.ftz.f32 %0, %1;" : "=f"(r) : "f"(x));
    return r;
}
__device__ __forceinline__ void cp16(uint32_t dst_smem, const void* src) {
    uint64_t g;
    asm("cvta.to.global.u64 %0, %1;" : "=l"(g) : "l"(src));
    asm volatile("cp.async.cg.shared.global [%0], [%1], 16;" :: "r"(dst_smem), "l"(g));
}
#define CP_COMMIT() asm volatile("cp.async.commit_group;" ::: "memory")

#define MMA_TF32(c, a0, a1, a2, a3, b0, b1)                                    \
    asm volatile("mma.sync.aligned.m16n8k8.row.col.f32.tf32.tf32.f32 "         \
                 "{%0,%1,%2,%3}, {%4,%5,%6,%7}, {%8,%9}, {%0,%1,%2,%3};"       \
                 : "+f"((c)[0]), "+f"((c)[1]), "+f"((c)[2]), "+f"((c)[3])      \
                 : "r"(a0), "r"(a1), "r"(a2), "r"(a3), "r"(b0), "r"(b1))

// ============================================================
// Pre-pass: round fp32 tensors to tf32 (rna) once per launch.
// ============================================================
__global__ __launch_bounds__(256) void prep_tf32(
    const float* __restrict__ x,
    const float* __restrict__ wq, const float* __restrict__ wk,
    const float* __restrict__ wv, const float* __restrict__ wo)
{
    const int z = blockIdx.y;
    const float* src;
    float* dst;
    int n4;
    if (z == 0)      { src = x;  dst = g_xt;            n4 = MM*DM/4; }
    else if (z == 1) { src = wq; dst = g_wt;            n4 = DM*DM/4; }
    else if (z == 2) { src = wk; dst = g_wt + DM*DM;    n4 = DM*DM/4; }
    else if (z == 3) { src = wv; dst = g_wt + 2*DM*DM;  n4 = DM*DM/4; }
    else             { src = wo; dst = g_wot;           n4 = DM*DM/4; }

    const int idx = blockIdx.x * 256 + threadIdx.x;
    if (idx >= n4) return;
    float4 v = ((const float4*)src)[idx];
    uint4 o;
    o.x = cvt_tf32(v.x); o.y = cvt_tf32(v.y);
    o.z = cvt_tf32(v.z); o.w = cvt_tf32(v.w);
    ((uint4*)dst)[idx] = o;
}

// ============================================================
// Single-pass tf32 tensor-core GEMM:  out = A @ W^T + bias
// A: [Mrows,1024] tf32 rm, W: [1024,1024] tf32 rm (k contiguous).
// CTA 128x128, BK=64, 512 threads (16 warps, 4x4, warp tile 32x32).
// SMEM: A/B fp32 tiles, padded stride 72 (conflict-free LDS.64 under
// the k-permutation 2qc/2qc+1 <-> qc/qc+4), 3-stage cp.async.
// MODE 0: QKV (blockIdx.z), epilogue scatters tf32 bits to g_q/g_k/g_v
// MODE 1: output projection, epilogue fp32 row-major to d_out
// ============================================================
#define ASTR     72
#define GTILE_B  (128*ASTR*4)        // 36864 bytes per 128x64 fp32 tile
#define GSTAGE_B (2*GTILE_B)         // A + B
#define GSTAGES  3
#define GEMM_SMEM_BYTES (1024 + GSTAGES*GSTAGE_B)

// one stage = A tile + B tile; 8 cp16 per thread (512 threads)
__device__ __forceinline__ void issue_stage(
    const float* __restrict__ Ag, const float* __restrict__ Bg,
    uint32_t st, int tid, int kb, int bm, int bn)
{
    #pragma unroll
    for (int t = 0; t < 4; t++) {
        const int id  = tid + t * 512;
        const int row = id >> 4;          // 0..127
        const int c4  = id & 15;          // float4 column
        const uint32_t so = (uint32_t)(row * ASTR + c4 * 4) * 4;
        cp16(st + so,           Ag + (size_t)(bm + row) * DM + kb * 64 + c4 * 4);
        cp16(st + GTILE_B + so, Bg + (size_t)(bn + row) * DM + kb * 64 + c4 * 4);
    }
}

template<int MODE>
__global__ __launch_bounds__(512, 1) void gemm_tc(
    const float* __restrict__ b1,
    const float* __restrict__ b2,
    const float* __restrict__ b3,
    float* __restrict__ outp)
{
    extern __shared__ char smraw[];
    char* tiles = (char*)(((uintptr_t)smraw + 1023) & ~(uintptr_t)1023);
    const uint32_t tiles32 = smem_u32(tiles);

    const int tid  = threadIdx.x;
    const int wid  = tid >> 5;
    const int lane = tid & 31;
    const int bm = blockIdx.y * 128;
    const int bn = blockIdx.x * 128;

    const float *Ag, *Bg;
    const float* bias;
    if (MODE == 0) {
        const int z = blockIdx.z;
        Ag = g_xt;
        Bg = g_wt + (size_t)z * DM * DM;
        bias = (z == 0) ? b1 : (z == 1) ? b2 : b3;
    } else {
        Ag = g_ct; Bg = g_wot; bias = b1;
    }

    const int qr = lane >> 2;            // 0..7
    const int qc = lane & 3;             // 0..3
    const int wm = (wid >> 2) * 32;
    const int wn = (wid & 3) * 32;

    float acc[2][4][4];
    #pragma unroll
    for (int i = 0; i < 2; i++)
        #pragma unroll
        for (int p = 0; p < 4; p++)
            #pragma unroll
            for (int c = 0; c < 4; c++) acc[i][p][c] = 0.f;

    issue_stage(Ag, Bg, tiles32 + 0*GSTAGE_B, tid, 0, bm, bn);
    CP_COMMIT();
    issue_stage(Ag, Bg, tiles32 + 1*GSTAGE_B, tid, 1, bm, bn);
    CP_COMMIT();

    int slot = 0;
    for (int kb = 0; kb < 16; kb++) {
        if (kb < 15) asm volatile("cp.async.wait_group 1;" ::: "memory");
        else         asm volatile("cp.async.wait_group 0;" ::: "memory");
        __syncthreads();

        if (kb + 2 < 16) {
            int ns = slot + 2; if (ns >= GSTAGES) ns -= GSTAGES;
            issue_stage(Ag, Bg, tiles32 + ns*GSTAGE_B, tid, kb + 2, bm, bn);
            CP_COMMIT();
        }

        const float* At = (const float*)(tiles + slot * GSTAGE_B);
        const float* Bt = (const float*)(tiles + slot * GSTAGE_B + GTILE_B);

        #pragma unroll
        for (int kk = 0; kk < 8; kk++) {
            const int cb = kk*8 + 2*qc;   // k-permuted float2 column
            uint32_t af[2][4];
            #pragma unroll
            for (int i = 0; i < 2; i++) {
                const int rl = wm + i*16 + qr;
                const float2 alo = *(const float2*)&At[rl*ASTR + cb];
                const float2 ahi = *(const float2*)&At[(rl+8)*ASTR + cb];
                af[i][0] = __float_as_uint(alo.x);
                af[i][1] = __float_as_uint(ahi.x);
                af[i][2] = __float_as_uint(alo.y);
                af[i][3] = __float_as_uint(ahi.y);
            }
            #pragma unroll
            for (int p = 0; p < 4; p++) {
                const float2 b2v = *(const float2*)&Bt[(wn + p*8 + qr)*ASTR + cb];
                const uint32_t b0 = __float_as_uint(b2v.x);
                const uint32_t b1 = __float_as_uint(b2v.y);
                #pragma unroll
                for (int i = 0; i < 2; i++)
                    MMA_TF32(acc[i][p], af[i][0], af[i][1], af[i][2], af[i][3], b0, b1);
            }
        }
        slot++; if (slot >= GSTAGES) slot = 0;
    }

    // ---- epilogue: D-fragment scatter + bias ----
    const int qrow = lane >> 2;
    const int qcol = (lane & 3) * 2;
    #pragma unroll
    for (int p = 0; p < 4; p++) {
        const int col = bn + wn + p*8 + qcol;
        const float bx = bias[col], by = bias[col + 1];
        #pragma unroll
        for (int i = 0; i < 2; i++) {
            const int row0 = bm + wm + i*16 + qrow;
            #pragma unroll
            for (int hh = 0; hh < 2; hh++) {
                const int row = row0 + hh*8;
                float ox = acc[i][p][2*hh+0] + bx;
                float oy = acc[i][p][2*hh+1] + by;
                if (MODE == 0) {
                    const int z = blockIdx.z;
                    float* out = (z == 0) ? g_q : (z == 1) ? g_k : g_v;
                    const int b = row >> 11;
                    const int s = row & 2047;
                    const int h = col >> 6;
                    const int d = col & 63;
                    float2 o;
                    o.x = __uint_as_float(cvt_tf32(ox));
                    o.y = __uint_as_float(cvt_tf32(oy));
                    *(float2*)(out + ((((size_t)b * NH + h) * SS + s) * DH + d)) = o;
                } else {
                    float2 o = make_float2(ox, oy);
                    *(float2*)(outp + (size_t)row * DM + col) = o;
                }
            }
        }
    }
}

// ============================================================
// Flash attention v3: tf32 mma.sync, causal, exp2-domain online softmax.
// 256 threads (8 warps), 128 q-rows/CTA, 64 keys/iter.
// cp.async double-buffered K/V; one __syncthreads per iteration.
// Epilogue writes ctx as tf32 (feeds tf32 out-projection).
// ============================================================
#define KSTR 72
#define VSTR 68
#define PSTR 72
#define ATT_SMEM_BYTES ((2*64*KSTR + 2*64*VSTR + 128*PSTR) * 4)

__global__ __launch_bounds__(256, 2) void attn_tc()
{
    extern __shared__ float smf[];
    float* Kbuf = smf;                              // [2][64*KSTR]
    float* Vbuf = smf + 2*64*KSTR;                  // [2][64*VSTR]
    float* Ps   = smf + 2*64*KSTR + 2*64*VSTR;      // [128*PSTR]
    const uint32_t KbufA = smem_u32(Kbuf);
    const uint32_t VbufA = smem_u32(Vbuf);

    const int tid  = threadIdx.x;
    const int lane = tid & 31;
    const int wid  = tid >> 5;                       // 0..7
    const int it   = (int)gridDim.x - 1 - (int)blockIdx.x;  // heavy tiles first
    const int bh   = blockIdx.y;

    const float* Qb = g_q + (size_t)bh * SS * DH;
    const float* Kb = g_k + (size_t)bh * SS * DH;
    const float* Vb = g_v + (size_t)bh * SS * DH;

    const int qr = lane >> 2;
    const int qc = lane & 3;
    const int row_lo = wid * 16 + qr;
    const int row_hi = row_lo + 8;
    const int qg_lo = it * 128 + row_lo;
    const int qg_hi = it * 128 + row_hi;

    // Q fragments, k-permuted
    uint32_t qf[8][4];
    #pragma unroll
    for (int kk = 0; kk < 8; kk++) {
        const float2 qlo = *(const float2*)&Qb[(size_t)qg_lo * DH + kk*8 + 2*qc];
        const float2 qhi = *(const float2*)&Qb[(size_t)qg_hi * DH + kk*8 + 2*qc];
        qf[kk][0] = __float_as_uint(qlo.x);
        qf[kk][1] = __float_as_uint(qhi.x);
        qf[kk][2] = __float_as_uint(qlo.y);
        qf[kk][3] = __float_as_uint(qhi.y);
    }

    const float SC = 0.18033688f;        // (1/8) * log2(e)
    float m0 = -1e30f, m1 = -1e30f, l0 = 0.f, l1 = 0.f;
    float o[8][4];
    #pragma unroll
    for (int nt = 0; nt < 8; nt++)
        #pragma unroll
        for (int c = 0; c < 4; c++) o[nt][c] = 0.f;

    // prologue: tile 0 into buffer 0
    {
        #pragma unroll
        for (int t2 = 0; t2 < 4; t2++) {
            const int id  = tid + t2 * 256;
            const int row = id >> 4;
            const int c   = (id & 15) * 4;
            cp16(KbufA + (uint32_t)(row*KSTR + c) * 4, Kb + (size_t)row * DH + c);
            cp16(VbufA + (uint32_t)(row*VSTR + c) * 4, Vb + (size_t)row * DH + c);
        }
        CP_COMMIT();
    }

    const int jtmax = 2 * it + 1;
    for (int jt = 0; jt <= jtmax; jt++) {
        asm volatile("cp.async.wait_group 0;" ::: "memory");
        __syncthreads();

        if (jt < jtmax) {
            const uint32_t kb = KbufA + (uint32_t)(((jt+1) & 1) * 64 * KSTR) * 4;
            const uint32_t vb = VbufA + (uint32_t)(((jt+1) & 1) * 64 * VSTR) * 4;
            const float* Kg = Kb + (size_t)(jt+1) * 64 * DH;
            const float* Vg = Vb + (size_t)(jt+1) * 64 * DH;
            #pragma unroll
            for (int t2 = 0; t2 < 4; t2++) {
                const int id  = tid + t2 * 256;
                const int row = id >> 4;
                const int c   = (id & 15) * 4;
                cp16(kb + (uint32_t)(row*KSTR + c) * 4, Kg + (size_t)row * DH + c);
                cp16(vb + (uint32_t)(row*VSTR + c) * 4, Vg + (size_t)row * DH + c);
            }
            CP_COMMIT();
        }

        const float* Ks = Kbuf + (jt & 1) * 64 * KSTR;
        const float* Vs = Vbuf + (jt & 1) * 64 * VSTR;

        // ---- S = Q K^T ----
        float s[8][4];
        #pragma unroll
        for (int nt = 0; nt < 8; nt++)
            #pragma unroll
            for (int c = 0; c < 4; c++) s[nt][c] = 0.f;

        #pragma unroll
        for (int kk = 0; kk < 8; kk++) {
            #pragma unroll
            for (int nt = 0; nt < 8; nt++) {
                const float2 b2v = *(const float2*)&Ks[(nt*8 + qr)*KSTR + kk*8 + 2*qc];
                MMA_TF32(s[nt], qf[kk][0], qf[kk][1], qf[kk][2], qf[kk][3],
                         __float_as_uint(b2v.x), __float_as_uint(b2v.y));
            }
        }

        // ---- causal mask ----
        if (jt >= 2*it) {
            #pragma unroll
            for (int nt = 0; nt < 8; nt++) {
                const int t0 = jt*64 + nt*8 + qc*2;
                if (t0     > qg_lo) s[nt][0] = -1e30f;
                if (t0 + 1 > qg_lo) s[nt][1] = -1e30f;
                if (t0     > qg_hi) s[nt][2] = -1e30f;
                if (t0 + 1 > qg_hi) s[nt][3] = -1e30f;
            }
        }

        // ---- online softmax (exp2 domain) ----
        float tm0 = -1e30f, tm1 = -1e30f;
        #pragma unroll
        for (int nt = 0; nt < 8; nt++) {
            tm0 = fmaxf(tm0, fmaxf(s[nt][0], s[nt][1]));
            tm1 = fmaxf(tm1, fmaxf(s[nt][2], s[nt][3]));
        }
        tm0 = fmaxf(tm0, __shfl_xor_sync(0xffffffffu, tm0, 1));
        tm0 = fmaxf(tm0, __shfl_xor_sync(0xffffffffu, tm0, 2));
        tm1 = fmaxf(tm1, __shfl_xor_sync(0xffffffffu, tm1, 1));
        tm1 = fmaxf(tm1, __shfl_xor_sync(0xffffffffu, tm1, 2));

        const float mn0 = fmaxf(m0, tm0);
        const float mn1 = fmaxf(m1, tm1);
        const float corr0 = ex2_fast((m0 - mn0) * SC);
        const float corr1 = ex2_fast((m1 - mn1) * SC);
        m0 = mn0; m1 = mn1;
        const float nms0 = -mn0 * SC;
        const float nms1 = -mn1 * SC;

        float ls0 = 0.f, ls1 = 0.f;
        #pragma unroll
        for (int nt = 0; nt < 8; nt++) {
            const float p0 = ex2_fast(fmaf(s[nt][0], SC, nms0));
            const float p1 = ex2_fast(fmaf(s[nt][1], SC, nms0));
            const float p2 = ex2_fast(fmaf(s[nt][2], SC, nms1));
            const float p3 = ex2_fast(fmaf(s[nt][3], SC, nms1));
            ls0 += p0 + p1;
            ls1 += p2 + p3;
            uint2 plo = make_uint2(cvt_tf32(p0), cvt_tf32(p1));
            uint2 phi = make_uint2(cvt_tf32(p2), cvt_tf32(p3));
            *(uint2*)&Ps[row_lo*PSTR + nt*8 + qc*2] = plo;
            *(uint2*)&Ps[row_hi*PSTR + nt*8 + qc*2] = phi;
        }
        ls0 += __shfl_xor_sync(0xffffffffu, ls0, 1);
        ls0 += __shfl_xor_sync(0xffffffffu, ls0, 2);
        ls1 += __shfl_xor_sync(0xffffffffu, ls1, 1);
        ls1 += __shfl_xor_sync(0xffffffffu, ls1, 2);
        l0 = l0 * corr0 + ls0;
        l1 = l1 * corr1 + ls1;

        #pragma unroll
        for (int nt = 0; nt < 8; nt++) {
            o[nt][0] *= corr0; o[nt][1] *= corr0;
            o[nt][2] *= corr1; o[nt][3] *= corr1;
        }
        __syncwarp();

        // ---- O += P V ----
        #pragma unroll
        for (int kt = 0; kt < 8; kt++) {
            const float2 alo = *(const float2*)&Ps[row_lo*PSTR + kt*8 + 2*qc];
            const float2 ahi = *(const float2*)&Ps[row_hi*PSTR + kt*8 + 2*qc];
            const uint32_t a0 = __float_as_uint(alo.x);
            const uint32_t a1 = __float_as_uint(ahi.x);
            const uint32_t a2 = __float_as_uint(alo.y);
            const uint32_t a3 = __float_as_uint(ahi.y);
            const int tr0 = (kt*8 + 2*qc) * VSTR;
            #pragma unroll
            for (int nt = 0; nt < 8; nt++) {
                const uint32_t b0 = __float_as_uint(Vs[tr0 + nt*8 + qr]);
                const uint32_t b1 = __float_as_uint(Vs[tr0 + VSTR + nt*8 + qr]);
                MMA_TF32(o[nt], a0, a1, a2, a3, b0, b1);
            }
        }
    }

    // ---- epilogue: normalize, write ctx as tf32 ----
    const int b = bh >> 4;
    const int h = bh & 15;
    const float i0 = 1.f / l0;
    const float i1 = 1.f / l1;
    const size_t r0off = (size_t)(b*SS + qg_lo) * DM;
    const size_t r1off = (size_t)(b*SS + qg_hi) * DM;
    #pragma unroll
    for (int nt = 0; nt < 8; nt++) {
        const int d = h*64 + nt*8 + qc*2;
        float2 w0, w1;
        w0.x = __uint_as_float(cvt_tf32(o[nt][0] * i0));
        w0.y = __uint_as_float(cvt_tf32(o[nt][1] * i0));
        w1.x = __uint_as_float(cvt_tf32(o[nt][2] * i1));
        w1.y = __uint_as_float(cvt_tf32(o[nt][3] * i1));
        *(float2*)&g_ct[r0off + d] = w0;
        *(float2*)&g_ct[r1off + d] = w1;
    }
}

// ============================================================
extern "C" void kernel_launch(void* const* d_in, const int* in_sizes, int n_in,
                              void* d_out, int out_size)
{
    const float* x  = (const float*)d_in[0];
    const float* Wq = (const float*)d_in[1];
    const float* bq = (const float*)d_in[2];
    const float* Wk = (const float*)d_in[3];
    const float* bk = (const float*)d_in[4];
    const float* Wv = (const float*)d_in[5];
    const float* bv = (const float*)d_in[6];
    const float* Wo = (const float*)d_in[7];
    const float* bo = (const float*)d_in[8];
    float* out = (float*)d_out;

    cudaFuncSetAttribute(gemm_tc<0>, cudaFuncAttributeMaxDynamicSharedMemorySize, GEMM_SMEM_BYTES);
    cudaFuncSetAttribute(gemm_tc<1>, cudaFuncAttributeMaxDynamicSharedMemorySize, GEMM_SMEM_BYTES);
    cudaFuncSetAttribute(attn_tc, cudaFuncAttributeMaxDynamicSharedMemorySize, ATT_SMEM_BYTES);

    prep_tf32<<<dim3(MM*DM/4/256, 5), 256>>>(x, Wq, Wk, Wv, Wo);
    gemm_tc<0><<<dim3(DM / 128, MM / 128, 3), 512, GEMM_SMEM_BYTES>>>(bq, bk, bv, nullptr);
    attn_tc<<<dim3(SS / 128, BB * NH), 256, ATT_SMEM_BYTES>>>();
    gemm_tc<1><<<dim3(DM / 128, MM / 128), 512, GEMM_SMEM_BYTES>>>(bo, nullptr, nullptr, out);
}

// round 17
// speedup vs baseline: 1.0843x; 1.0843x over previous
#include <cuda_runtime.h>
#include <cuda_bf16.h>
#include <cstdint>
#include <math.h>

// Problem constants
#define BB   2
#define SS   2048
#define DM   1024
#define NH   16
#define DH   64
#define MM   (BB*SS)

// -------- scratch (device globals; allocation-free) --------
__device__ float g_q[BB*NH*SS*DH];                       // [b][h][s][d] tf32 bits
__device__ float g_k[BB*NH*SS*DH];
__device__ float g_v[BB*NH*SS*DH];
__device__ __align__(16) __nv_bfloat16 g_xhi[MM*DM];     // X split
__device__ __align__(16) __nv_bfloat16 g_xlo[MM*DM];
__device__ __align__(16) __nv_bfloat16 g_whi[3*DM*DM];   // Wq,Wk,Wv split
__device__ __align__(16) __nv_bfloat16 g_wlo[3*DM*DM];
__device__ __align__(16) __nv_bfloat16 g_wohi[DM*DM];    // Wo split
__device__ __align__(16) __nv_bfloat16 g_wolo[DM*DM];
__device__ __align__(16) __nv_bfloat16 g_chi[MM*DM];     // ctx split (attention out)
__device__ __align__(16) __nv_bfloat16 g_clo[MM*DM];

// ============================================================
// helpers
// ============================================================
__device__ __forceinline__ uint32_t smem_u32(const void* p) {
    uint32_t a;
    asm("{ .reg .u64 t; cvta.to.shared.u64 t, %1; cvt.u32.u64 %0, t; }" : "=r"(a) : "l"(p));
    return a;
}
__device__ __forceinline__ uint32_t cvt_tf32(float a) {
    uint32_t r;
    asm("cvt.rna.tf32.f32 %0, %1;" : "=r"(r) : "f"(a));
    return r;
}
__device__ __forceinline__ float ex2_fast(float x) {
    float r;
    asm("ex2.approx.ftz.f32 %0, %1;" : "=f"(r) : "f"(x));
    return r;
}
__device__ __forceinline__ void cp16(uint32_t dst_smem, const void* src) {
    uint64_t g;
    asm("cvta.to.global.u64 %0, %1;" : "=l"(g) : "l"(src));
    asm volatile("cp.async.cg.shared.global [%0], [%1], 16;" :: "r"(dst_smem), "l"(g));
}
#define CP_COMMIT() asm volatile("cp.async.commit_group;" ::: "memory")

#define LDSM4(d0, d1, d2, d3, addr)                                            \
    asm volatile("ldmatrix.sync.aligned.m8n8.x4.shared.b16 {%0,%1,%2,%3}, [%4];" \
                 : "=r"(d0), "=r"(d1), "=r"(d2), "=r"(d3) : "r"(addr))

#define MMA16816(c, a0, a1, a2, a3, b0, b1)                                    \
    asm volatile("mma.sync.aligned.m16n8k16.row.col.f32.bf16.bf16.f32 "        \
                 "{%0,%1,%2,%3}, {%4,%5,%6,%7}, {%8,%9}, {%0,%1,%2,%3};"       \
                 : "+f"((c)[0]), "+f"((c)[1]), "+f"((c)[2]), "+f"((c)[3])      \
                 : "r"(a0), "r"(a1), "r"(a2), "r"(a3), "r"(b0), "r"(b1))

#define MMA_TF32(c, a0, a1, a2, a3, b0, b1)                                    \
    asm volatile("mma.sync.aligned.m16n8k8.row.col.f32.tf32.tf32.f32 "         \
                 "{%0,%1,%2,%3}, {%4,%5,%6,%7}, {%8,%9}, {%0,%1,%2,%3};"       \
                 : "+f"((c)[0]), "+f"((c)[1]), "+f"((c)[2]), "+f"((c)[3])      \
                 : "r"(a0), "r"(a1), "r"(a2), "r"(a3), "r"(b0), "r"(b1))

// ============================================================
// Pre-pass: split fp32 tensors into bf16 hi/lo (once per launch).
// ============================================================
__global__ __launch_bounds__(256) void prep_split(
    const float* __restrict__ x,
    const float* __restrict__ wq, const float* __restrict__ wk,
    const float* __restrict__ wv, const float* __restrict__ wo)
{
    const int z = blockIdx.y;
    const float* src;
    __nv_bfloat16* hi;
    __nv_bfloat16* lo;
    int n4;
    if (z == 0)      { src = x;  hi = g_xhi;             lo = g_xlo;             n4 = MM*DM/4; }
    else if (z == 1) { src = wq; hi = g_whi;             lo = g_wlo;             n4 = DM*DM/4; }
    else if (z == 2) { src = wk; hi = g_whi + DM*DM;     lo = g_wlo + DM*DM;     n4 = DM*DM/4; }
    else if (z == 3) { src = wv; hi = g_whi + 2*DM*DM;   lo = g_wlo + 2*DM*DM;   n4 = DM*DM/4; }
    else             { src = wo; hi = g_wohi;            lo = g_wolo;            n4 = DM*DM/4; }

    const int idx = blockIdx.x * 256 + threadIdx.x;
    if (idx >= n4) return;
    float4 v = ((const float4*)src)[idx];
    __nv_bfloat162 h01 = __floats2bfloat162_rn(v.x, v.y);
    __nv_bfloat162 h23 = __floats2bfloat162_rn(v.z, v.w);
    __nv_bfloat162 l01 = __floats2bfloat162_rn(v.x - __bfloat162float(h01.x),
                                               v.y - __bfloat162float(h01.y));
    __nv_bfloat162 l23 = __floats2bfloat162_rn(v.z - __bfloat162float(h23.x),
                                               v.w - __bfloat162float(h23.y));
    ((__nv_bfloat162*)hi)[2*idx]   = h01;
    ((__nv_bfloat162*)hi)[2*idx+1] = h23;
    ((__nv_bfloat162*)lo)[2*idx]   = l01;
    ((__nv_bfloat162*)lo)[2*idx+1] = l23;
}

// ============================================================
// bf16-split tensor-core GEMM, 2 CTAs/SM:  out = A @ W^T + bias
// CTA tile 128x64, BK=64, 256 threads (8 warps, 4m x 2n, warp tile 32x32).
// 2-stage cp.async, 48KB/stage, 96KB/CTA -> 2 CTAs co-resident per SM so
// one CTA's barriers overlap the other's compute (R13: 1 CTA/SM, tensor 52%).
// MODE 0: QKV (blockIdx.z), epilogue scatters tf32 bits to g_q/g_k/g_v
// MODE 1: output projection, epilogue fp32 row-major to d_out
// ============================================================
#define ATILE_B  16384               // 128x64 bf16
#define BTILE_B  8192                // 64x64 bf16
#define GSTAGE_B (2*ATILE_B + 2*BTILE_B)   // Ahi Alo Bhi Blo = 48KB
#define GSTAGES  2
#define GEMM_SMEM_BYTES (1024 + GSTAGES*GSTAGE_B)

// one stage: A 128 rows (8 cp16 per thread), B 64 rows (4 cp16 per thread)
__device__ __forceinline__ void issue_stage(
    const __nv_bfloat16* __restrict__ Ah, const __nv_bfloat16* __restrict__ Al,
    const __nv_bfloat16* __restrict__ Bh, const __nv_bfloat16* __restrict__ Bl,
    uint32_t st, int tid, int kb, int bm, int bn)
{
    #pragma unroll
    for (int t = 0; t < 4; t++) {
        const int id = tid + t * 256;
        const int r  = id >> 3;          // 0..127
        const int c  = id & 7;
        const uint32_t sw = (uint32_t)(r * 128 + ((c ^ (r & 7)) << 4));
        const size_t ga = (size_t)(bm + r) * DM + kb * 64 + c * 8;
        cp16(st + sw,           Ah + ga);
        cp16(st + ATILE_B + sw, Al + ga);
    }
    #pragma unroll
    for (int t = 0; t < 2; t++) {
        const int id = tid + t * 256;
        const int r  = id >> 3;          // 0..63
        const int c  = id & 7;
        const uint32_t sw = (uint32_t)(r * 128 + ((c ^ (r & 7)) << 4));
        const size_t gb = (size_t)(bn + r) * DM + kb * 64 + c * 8;
        cp16(st + 2*ATILE_B + sw,           Bh + gb);
        cp16(st + 2*ATILE_B + BTILE_B + sw, Bl + gb);
    }
}

template<int MODE>
__global__ __launch_bounds__(256, 2) void gemm_tc(
    const float* __restrict__ b1,
    const float* __restrict__ b2,
    const float* __restrict__ b3,
    float* __restrict__ outp)
{
    extern __shared__ char smraw[];
    char* tiles = (char*)(((uintptr_t)smraw + 1023) & ~(uintptr_t)1023);
    const uint32_t tiles32 = smem_u32(tiles);

    const int tid  = threadIdx.x;
    const int wid  = tid >> 5;
    const int lane = tid & 31;
    const int bm = blockIdx.y * 128;
    const int bn = blockIdx.x * 64;

    const __nv_bfloat16 *Ah, *Al, *Bh, *Bl;
    const float* bias;
    if (MODE == 0) {
        const int z = blockIdx.z;
        Ah = g_xhi; Al = g_xlo;
        Bh = g_whi + (size_t)z * DM * DM;
        Bl = g_wlo + (size_t)z * DM * DM;
        bias = (z == 0) ? b1 : (z == 1) ? b2 : b3;
    } else {
        Ah = g_chi; Al = g_clo; Bh = g_wohi; Bl = g_wolo;
        bias = b1;
    }

    // ldmatrix lane addressing
    const int lrow = (lane & 7) | (((lane >> 3) & 1) << 3);  // 0..15
    const int lkh  = lane >> 4;                              // k half 0/1
    const int r7   = lane & 7;
    const int wm   = (wid >> 1) * 32;    // warp m offset (0/32/64/96)
    const int wn   = (wid & 1) * 32;     // warp n offset (0/32)

    float acc[2][4][4];
    #pragma unroll
    for (int i = 0; i < 2; i++)
        #pragma unroll
        for (int j = 0; j < 4; j++)
            #pragma unroll
            for (int c = 0; c < 4; c++) acc[i][j][c] = 0.f;

    // prologue: both stages in flight
    issue_stage(Ah, Al, Bh, Bl, tiles32 + 0*GSTAGE_B, tid, 0, bm, bn);
    CP_COMMIT();
    issue_stage(Ah, Al, Bh, Bl, tiles32 + 1*GSTAGE_B, tid, 1, bm, bn);
    CP_COMMIT();

    for (int kb = 0; kb < 16; kb++) {
        if (kb < 15) asm volatile("cp.async.wait_group 1;" ::: "memory");
        else         asm volatile("cp.async.wait_group 0;" ::: "memory");
        __syncthreads();

        const uint32_t Ahi = tiles32 + (kb & 1) * GSTAGE_B;
        const uint32_t Alo = Ahi + ATILE_B;
        const uint32_t Bhi = Ahi + 2*ATILE_B;
        const uint32_t Blo = Ahi + 2*ATILE_B + BTILE_B;

        #pragma unroll
        for (int k16 = 0; k16 < 4; k16++) {
            uint32_t ahi[2][4], alo[2][4], bhi[2][4], blo[2][4];
            const int ck = ((2*k16 + lkh) ^ r7) * 16;
            #pragma unroll
            for (int i = 0; i < 2; i++) {
                const uint32_t ro = (uint32_t)(wm + i*16 + lrow) * 128 + ck;
                LDSM4(ahi[i][0], ahi[i][1], ahi[i][2], ahi[i][3], Ahi + ro);
                LDSM4(alo[i][0], alo[i][1], alo[i][2], alo[i][3], Alo + ro);
            }
            #pragma unroll
            for (int p = 0; p < 2; p++) {
                const uint32_t ro = (uint32_t)(wn + p*16 + lrow) * 128 + ck;
                LDSM4(bhi[p][0], bhi[p][1], bhi[p][2], bhi[p][3], Bhi + ro);
                LDSM4(blo[p][0], blo[p][1], blo[p][2], blo[p][3], Blo + ro);
            }
            #pragma unroll
            for (int i = 0; i < 2; i++)
                #pragma unroll
                for (int jn = 0; jn < 4; jn++) {
                    const int p = jn >> 1, q = jn & 1;
                    MMA16816(acc[i][jn], ahi[i][0], ahi[i][1], ahi[i][2], ahi[i][3],
                             bhi[p][q], bhi[p][q+2]);
                    MMA16816(acc[i][jn], ahi[i][0], ahi[i][1], ahi[i][2], ahi[i][3],
                             blo[p][q], blo[p][q+2]);
                    MMA16816(acc[i][jn], alo[i][0], alo[i][1], alo[i][2], alo[i][3],
                             bhi[p][q], bhi[p][q+2]);
                }
        }

        __syncthreads();   // all warps done reading this slot
        if (kb + 2 < 16) {
            issue_stage(Ah, Al, Bh, Bl, tiles32 + (kb & 1) * GSTAGE_B, tid, kb + 2, bm, bn);
            CP_COMMIT();
        }
    }

    // ---- epilogue: D-fragment scatter + bias ----
    const int qrow = lane >> 2;
    const int qcol = (lane & 3) * 2;
    #pragma unroll
    for (int jn = 0; jn < 4; jn++) {
        const int col = bn + wn + jn*8 + qcol;
        const float bx = bias[col], by = bias[col + 1];
        #pragma unroll
        for (int i = 0; i < 2; i++) {
            const int row0 = bm + wm + i*16 + qrow;
            #pragma unroll
            for (int hh = 0; hh < 2; hh++) {
                const int row = row0 + hh*8;
                float ox = acc[i][jn][2*hh+0] + bx;
                float oy = acc[i][jn][2*hh+1] + by;
                if (MODE == 0) {
                    const int z = blockIdx.z;
                    float* out = (z == 0) ? g_q : (z == 1) ? g_k : g_v;
                    const int b = row >> 11;
                    const int s = row & 2047;
                    const int h = col >> 6;
                    const int d = col & 63;
                    float2 o;
                    o.x = __uint_as_float(cvt_tf32(ox));
                    o.y = __uint_as_float(cvt_tf32(oy));
                    *(float2*)(out + ((((size_t)b * NH + h) * SS + s) * DH + d)) = o;
                } else {
                    float2 o = make_float2(ox, oy);
                    *(float2*)(outp + (size_t)row * DM + col) = o;
                }
            }
        }
    }
}

// ============================================================
// Flash attention v3 (R13, verified): tf32 mma.sync, causal,
// exp2-domain online softmax, 256 threads, 128 q-rows/CTA,
// cp.async double-buffered K/V, bf16 hi/lo ctx epilogue.
// ============================================================
#define KSTR 72
#define VSTR 68
#define PSTR 72
#define ATT_SMEM_BYTES ((2*64*KSTR + 2*64*VSTR + 128*PSTR) * 4)

__global__ __launch_bounds__(256, 2) void attn_tc()
{
    extern __shared__ float smf[];
    float* Kbuf = smf;                              // [2][64*KSTR]
    float* Vbuf = smf + 2*64*KSTR;                  // [2][64*VSTR]
    float* Ps   = smf + 2*64*KSTR + 2*64*VSTR;      // [128*PSTR]
    const uint32_t KbufA = smem_u32(Kbuf);
    const uint32_t VbufA = smem_u32(Vbuf);

    const int tid  = threadIdx.x;
    const int lane = tid & 31;
    const int wid  = tid >> 5;                       // 0..7
    const int it   = (int)gridDim.x - 1 - (int)blockIdx.x;  // heavy tiles first
    const int bh   = blockIdx.y;

    const float* Qb = g_q + (size_t)bh * SS * DH;
    const float* Kb = g_k + (size_t)bh * SS * DH;
    const float* Vb = g_v + (size_t)bh * SS * DH;

    const int qr = lane >> 2;
    const int qc = lane & 3;
    const int row_lo = wid * 16 + qr;
    const int row_hi = row_lo + 8;
    const int qg_lo = it * 128 + row_lo;
    const int qg_hi = it * 128 + row_hi;

    // Q fragments, k-permuted: logical k=qc -> phys 2qc, k=qc+4 -> 2qc+1
    uint32_t qf[8][4];
    #pragma unroll
    for (int kk = 0; kk < 8; kk++) {
        const float2 qlo = *(const float2*)&Qb[(size_t)qg_lo * DH + kk*8 + 2*qc];
        const float2 qhi = *(const float2*)&Qb[(size_t)qg_hi * DH + kk*8 + 2*qc];
        qf[kk][0] = __float_as_uint(qlo.x);
        qf[kk][1] = __float_as_uint(qhi.x);
        qf[kk][2] = __float_as_uint(qlo.y);
        qf[kk][3] = __float_as_uint(qhi.y);
    }

    const float SC = 0.18033688f;        // (1/8) * log2(e)
    float m0 = -1e30f, m1 = -1e30f, l0 = 0.f, l1 = 0.f;
    float o[8][4];
    #pragma unroll
    for (int nt = 0; nt < 8; nt++)
        #pragma unroll
        for (int c = 0; c < 4; c++) o[nt][c] = 0.f;

    // prologue: tile 0 into buffer 0
    {
        #pragma unroll
        for (int t2 = 0; t2 < 4; t2++) {
            const int id  = tid + t2 * 256;
            const int row = id >> 4;
            const int c   = (id & 15) * 4;
            cp16(KbufA + (uint32_t)(row*KSTR + c) * 4, Kb + (size_t)row * DH + c);
            cp16(VbufA + (uint32_t)(row*VSTR + c) * 4, Vb + (size_t)row * DH + c);
        }
        CP_COMMIT();
    }

    const int jtmax = 2 * it + 1;
    for (int jt = 0; jt <= jtmax; jt++) {
        asm volatile("cp.async.wait_group 0;" ::: "memory");
        __syncthreads();

        if (jt < jtmax) {
            const uint32_t kb = KbufA + (uint32_t)(((jt+1) & 1) * 64 * KSTR) * 4;
            const uint32_t vb = VbufA + (uint32_t)(((jt+1) & 1) * 64 * VSTR) * 4;
            const float* Kg = Kb + (size_t)(jt+1) * 64 * DH;
            const float* Vg = Vb + (size_t)(jt+1) * 64 * DH;
            #pragma unroll
            for (int t2 = 0; t2 < 4; t2++) {
                const int id  = tid + t2 * 256;
                const int row = id >> 4;
                const int c   = (id & 15) * 4;
                cp16(kb + (uint32_t)(row*KSTR + c) * 4, Kg + (size_t)row * DH + c);
                cp16(vb + (uint32_t)(row*VSTR + c) * 4, Vg + (size_t)row * DH + c);
            }
            CP_COMMIT();
        }

        const float* Ks = Kbuf + (jt & 1) * 64 * KSTR;
        const float* Vs = Vbuf + (jt & 1) * 64 * VSTR;

        // ---- S = Q K^T ----
        float s[8][4];
        #pragma unroll
        for (int nt = 0; nt < 8; nt++)
            #pragma unroll
            for (int c = 0; c < 4; c++) s[nt][c] = 0.f;

        #pragma unroll
        for (int kk = 0; kk < 8; kk++) {
            #pragma unroll
            for (int nt = 0; nt < 8; nt++) {
                const float2 b2v = *(const float2*)&Ks[(nt*8 + qr)*KSTR + kk*8 + 2*qc];
                MMA_TF32(s[nt], qf[kk][0], qf[kk][1], qf[kk][2], qf[kk][3],
                         __float_as_uint(b2v.x), __float_as_uint(b2v.y));
            }
        }

        // ---- causal mask (last two key tiles only) ----
        if (jt >= 2*it) {
            #pragma unroll
            for (int nt = 0; nt < 8; nt++) {
                const int t0 = jt*64 + nt*8 + qc*2;
                if (t0     > qg_lo) s[nt][0] = -1e30f;
                if (t0 + 1 > qg_lo) s[nt][1] = -1e30f;
                if (t0     > qg_hi) s[nt][2] = -1e30f;
                if (t0 + 1 > qg_hi) s[nt][3] = -1e30f;
            }
        }

        // ---- online softmax (exp2 domain) ----
        float tm0 = -1e30f, tm1 = -1e30f;
        #pragma unroll
        for (int nt = 0; nt < 8; nt++) {
            tm0 = fmaxf(tm0, fmaxf(s[nt][0], s[nt][1]));
            tm1 = fmaxf(tm1, fmaxf(s[nt][2], s[nt][3]));
        }
        tm0 = fmaxf(tm0, __shfl_xor_sync(0xffffffffu, tm0, 1));
        tm0 = fmaxf(tm0, __shfl_xor_sync(0xffffffffu, tm0, 2));
        tm1 = fmaxf(tm1, __shfl_xor_sync(0xffffffffu, tm1, 1));
        tm1 = fmaxf(tm1, __shfl_xor_sync(0xffffffffu, tm1, 2));

        const float mn0 = fmaxf(m0, tm0);
        const float mn1 = fmaxf(m1, tm1);
        const float corr0 = ex2_fast((m0 - mn0) * SC);
        const float corr1 = ex2_fast((m1 - mn1) * SC);
        m0 = mn0; m1 = mn1;
        const float nms0 = -mn0 * SC;
        const float nms1 = -mn1 * SC;

        float ls0 = 0.f, ls1 = 0.f;
        #pragma unroll
        for (int nt = 0; nt < 8; nt++) {
            const float p0 = ex2_fast(fmaf(s[nt][0], SC, nms0));
            const float p1 = ex2_fast(fmaf(s[nt][1], SC, nms0));
            const float p2 = ex2_fast(fmaf(s[nt][2], SC, nms1));
            const float p3 = ex2_fast(fmaf(s[nt][3], SC, nms1));
            ls0 += p0 + p1;
            ls1 += p2 + p3;
            uint2 plo = make_uint2(cvt_tf32(p0), cvt_tf32(p1));
            uint2 phi = make_uint2(cvt_tf32(p2), cvt_tf32(p3));
            *(uint2*)&Ps[row_lo*PSTR + nt*8 + qc*2] = plo;
            *(uint2*)&Ps[row_hi*PSTR + nt*8 + qc*2] = phi;
        }
        ls0 += __shfl_xor_sync(0xffffffffu, ls0, 1);
        ls0 += __shfl_xor_sync(0xffffffffu, ls0, 2);
        ls1 += __shfl_xor_sync(0xffffffffu, ls1, 1);
        ls1 += __shfl_xor_sync(0xffffffffu, ls1, 2);
        l0 = l0 * corr0 + ls0;
        l1 = l1 * corr1 + ls1;

        #pragma unroll
        for (int nt = 0; nt < 8; nt++) {
            o[nt][0] *= corr0; o[nt][1] *= corr0;
            o[nt][2] *= corr1; o[nt][3] *= corr1;
        }
        __syncwarp();

        // ---- O += P V ----
        #pragma unroll
        for (int kt = 0; kt < 8; kt++) {
            const float2 alo = *(const float2*)&Ps[row_lo*PSTR + kt*8 + 2*qc];
            const float2 ahi = *(const float2*)&Ps[row_hi*PSTR + kt*8 + 2*qc];
            const uint32_t a0 = __float_as_uint(alo.x);
            const uint32_t a1 = __float_as_uint(ahi.x);
            const uint32_t a2 = __float_as_uint(alo.y);
            const uint32_t a3 = __float_as_uint(ahi.y);
            const int tr0 = (kt*8 + 2*qc) * VSTR;
            #pragma unroll
            for (int nt = 0; nt < 8; nt++) {
                const uint32_t b0 = __float_as_uint(Vs[tr0 + nt*8 + qr]);
                const uint32_t b1 = __float_as_uint(Vs[tr0 + VSTR + nt*8 + qr]);
                MMA_TF32(o[nt], a0, a1, a2, a3, b0, b1);
            }
        }
    }

    // ---- epilogue: normalize, split to bf16 hi/lo ctx ----
    const int b = bh >> 4;
    const int h = bh & 15;
    const float i0 = 1.f / l0;
    const float i1 = 1.f / l1;
    const size_t r0off = (size_t)(b*SS + qg_lo) * DM;
    const size_t r1off = (size_t)(b*SS + qg_hi) * DM;
    #pragma unroll
    for (int nt = 0; nt < 8; nt++) {
        const int d = h*64 + nt*8 + qc*2;
        float w0x = o[nt][0] * i0, w0y = o[nt][1] * i0;
        float w1x = o[nt][2] * i1, w1y = o[nt][3] * i1;
        __nv_bfloat162 h0 = __floats2bfloat162_rn(w0x, w0y);
        __nv_bfloat162 h1 = __floats2bfloat162_rn(w1x, w1y);
        __nv_bfloat162 l0v = __floats2bfloat162_rn(w0x - __bfloat162float(h0.x),
                                                   w0y - __bfloat162float(h0.y));
        __nv_bfloat162 l1v = __floats2bfloat162_rn(w1x - __bfloat162float(h1.x),
                                                   w1y - __bfloat162float(h1.y));
        *(__nv_bfloat162*)&g_chi[r0off + d] = h0;
        *(__nv_bfloat162*)&g_clo[r0off + d] = l0v;
        *(__nv_bfloat162*)&g_chi[r1off + d] = h1;
        *(__nv_bfloat162*)&g_clo[r1off + d] = l1v;
    }
}

// ============================================================
extern "C" void kernel_launch(void* const* d_in, const int* in_sizes, int n_in,
                              void* d_out, int out_size)
{
    const float* x  = (const float*)d_in[0];
    const float* Wq = (const float*)d_in[1];
    const float* bq = (const float*)d_in[2];
    const float* Wk = (const float*)d_in[3];
    const float* bk = (const float*)d_in[4];
    const float* Wv = (const float*)d_in[5];
    const float* bv = (const float*)d_in[6];
    const float* Wo = (const float*)d_in[7];
    const float* bo = (const float*)d_in[8];
    float* out = (float*)d_out;

    cudaFuncSetAttribute(gemm_tc<0>, cudaFuncAttributeMaxDynamicSharedMemorySize, GEMM_SMEM_BYTES);
    cudaFuncSetAttribute(gemm_tc<1>, cudaFuncAttributeMaxDynamicSharedMemorySize, GEMM_SMEM_BYTES);
    cudaFuncSetAttribute(attn_tc, cudaFuncAttributeMaxDynamicSharedMemorySize, ATT_SMEM_BYTES);

    prep_split<<<dim3(MM*DM/4/256, 5), 256>>>(x, Wq, Wk, Wv, Wo);
    gemm_tc<0><<<dim3(DM / 64, MM / 128, 3), 256, GEMM_SMEM_BYTES>>>(bq, bk, bv, nullptr);
    attn_tc<<<dim3(SS / 128, BB * NH), 256, ATT_SMEM_BYTES>>>();
    gemm_tc<1><<<dim3(DM / 64, MM / 128), 256, GEMM_SMEM_BYTES>>>(bo, nullptr, nullptr, out);
}